// round 13
// baseline (speedup 1.0000x reference)
#include <cuda_runtime.h>
#include <math.h>

#define TQ 64
#define IQ 9
#define NQ 128
#define VQ 20
#define CQ 100
#define OQ 8
#define GQ 4
#define BLK 128
#define EPSQ 1e-8f
#define PBLK 96
#define HTS 128   // h_t row: h(100) | r(20) | zero pad(8)

// p_s per-g block (96 floats), vector-aligned:
//  0..19 kr | 20..22 sr, 23 gammar | 24 betar, 25 gr, 26 betaw, 27 gw
//  28..30 sw, 31 gammaw | 32..51 kw | 52..71 e | 72..91 a | 92..95 pad

// 4-j interleaved weights: W4[jb][col][q] = W[(4jb+q)*od + col]
__device__ __align__(16) float Wc4_g[8 * CQ * 4];    // 3200 (j padded 29->32)
__device__ __align__(16) float Wr4_g[25 * 26 * 4];   // 2600
__device__ __align__(16) float Ww4_g[25 * 66 * 4];   // 6600
__device__ __align__(16) float Wf4_g[32 * OQ * 4];   // 4096 (j padded 120->128)

__global__ void prep_kernel(const float* __restrict__ Wc, const float* __restrict__ Wr,
                            const float* __restrict__ Ww, const float* __restrict__ Wf) {
    int i = blockIdx.x * blockDim.x + threadIdx.x;
    if (i < 3200) {
        int jb = i / 400, rem = i % 400, c = rem >> 2, q = rem & 3, j = jb * 4 + q;
        Wc4_g[i] = (j < 29) ? Wc[j * CQ + c] : 0.f;
    }
    int j2 = i - 3200;
    if (j2 >= 0 && j2 < 2600) {
        int jb = j2 / 104, rem = j2 % 104, c = rem >> 2, q = rem & 3;
        Wr4_g[j2] = Wr[(jb * 4 + q) * 26 + c];
    }
    int k2 = i - 5800;
    if (k2 >= 0 && k2 < 6600) {
        int jb = k2 / 264, rem = k2 % 264, c = rem >> 2, q = rem & 3;
        Ww4_g[k2] = Ww[(jb * 4 + q) * 66 + c];
    }
    int l2 = i - 12400;
    if (l2 >= 0 && l2 < 4096) {
        int jb = l2 / 32, rem = l2 % 32, o = rem >> 2, q = rem & 3, j = jb * 4 + q;
        Wf4_g[l2] = (j < 120) ? Wf[j * OQ + o] : 0.f;
    }
}

typedef unsigned long long ull;
__device__ __forceinline__ ull pk2(float v) {
    ull r; asm("mov.b64 %0, {%1, %1};" : "=l"(r) : "f"(v)); return r;
}
__device__ __forceinline__ float2 upk2(ull v) {
    float2 r; asm("mov.b64 {%0, %1}, %2;" : "=f"(r.x), "=f"(r.y) : "l"(v)); return r;
}
__device__ __forceinline__ ull ffma2(ull a, ull b, ull c) {
    ull d; asm("fma.rn.f32x2 %0, %1, %2, %3;" : "=l"(d) : "l"(a), "l"(b), "l"(c)); return d;
}
__device__ __forceinline__ ull fmul2(ull a, ull b) {
    ull d; asm("mul.rn.f32x2 %0, %1, %2;" : "=l"(d) : "l"(a), "l"(b)); return d;
}
__device__ __forceinline__ ull fadd2(ull a, ull b) {
    ull d; asm("add.rn.f32x2 %0, %1, %2;" : "=l"(d) : "l"(a), "l"(b)); return d;
}
__device__ __forceinline__ ull d2l(double v) { return __double_as_longlong(v); }

__device__ __forceinline__ float ftanh_(float x) {
    float xc = fminf(fmaxf(x, -15.f), 15.f);
    float e = __expf(2.f * xc);
    return __fdividef(e - 1.f, e + 1.f);
}
__device__ __forceinline__ float fsoftplus_(float x) {
    return fmaxf(x, 0.f) + __logf(1.f + __expf(-fabsf(x)));
}
__device__ __forceinline__ float fsigmoid_(float x) {
    return __fdividef(1.f, 1.f + __expf(-x));
}
__device__ __forceinline__ float apply_act(int at, float v) {
    switch (at) {
        case 0:  return ftanh_(v);
        case 1:  return fsoftplus_(v);
        case 2:  return fsigmoid_(v);
        case 3:  return __expf(v);
        default: return 1.f + fsoftplus_(v);
    }
}
__device__ __forceinline__ float warp_sum(float v) {
    v += __shfl_xor_sync(0xffffffffu, v, 16);
    v += __shfl_xor_sync(0xffffffffu, v, 8);
    v += __shfl_xor_sync(0xffffffffu, v, 4);
    v += __shfl_xor_sync(0xffffffffu, v, 2);
    v += __shfl_xor_sync(0xffffffffu, v, 1);
    return v;
}
__device__ __forceinline__ ull warp_sum2(ull v) {
    #pragma unroll
    for (int k = 16; k; k >>= 1) {
        ull o = __shfl_xor_sync(0xffffffffu, v, k);
        asm("add.rn.f32x2 %0, %0, %1;" : "+l"(v) : "l"(o));
    }
    return v;
}

__global__ __launch_bounds__(BLK, 3) void ntm_kernel(
    const float* __restrict__ x,
    const float* __restrict__ bc, const float* __restrict__ br,
    const float* __restrict__ bw, const float* __restrict__ bf,
    const float* __restrict__ r_bias, const float* __restrict__ M_bias,
    float* __restrict__ out)
{
    extern __shared__ float sm[];
    float* z_s = sm;                        // [32][G]  controller input (x|r|pad)
    float* h_s = z_s + 32 * GQ;             // [100][G] controller hidden
    float* p_s = h_s + CQ * GQ;             // [G][96]  head params
    float* h_t = p_s + GQ * PBLK;           // [G][128] [h|r|pad] per-g contiguous

    const int tid  = threadIdx.x;
    const int lane = tid & 31;
    const int g    = tid >> 5;              // warp == batch element
    const int b0   = blockIdx.x * GQ;

    // ---- hoisted per-thread constants ----
    float bcv = (tid < CQ) ? bc[tid] : 0.f;
    const float4* Wp4 = (const float4*)Ww4_g;
    int od = 66, st = 0, at = 0; float bsv = 0.f;
    {
        bool rh = (tid < 26);
        int c = rh ? tid : tid - 26;
        if (rh)            { Wp4 = (const float4*)Wr4_g + c; od = 26; bsv = br[c]; }
        else if (tid < 92) { Wp4 = (const float4*)Ww4_g + c; bsv = bw[c]; }
        if      (c < 20)  { st = (rh ? 0 : 32) + c;       at = 0; }
        else if (c == 20) { st = rh ? 24 : 26;            at = 1; }
        else if (c == 21) { st = rh ? 25 : 27;            at = 2; }
        else if (c < 25)  { st = (rh ? 20 : 28) + (c-22); at = 3; }
        else if (c == 25) { st = rh ? 23 : 31;            at = 4; }
        else if (c < 46)  { st = 52 + (c - 26);           at = 2; }
        else              { st = 72 + (c - 46);           at = 0; }
    }
    float bfv = bf[lane & 7];
    const float* pg = p_s + g * PBLK;

    // ---- M lives in REGISTERS: lane owns rows lane+32i of batch g ----
    // M_r[i][2c], M_r[i][2c+1] = packed pairs of row's float4 chunk c
    ull M_r[4][10];
    float wprev_r[GQ];
    {
        #pragma unroll
        for (int i = 0; i < GQ; i++) {
            int n = lane + 32 * i;
            wprev_r[i] = 0.f;
            const double2* Mb2 = (const double2*)(M_bias + n * VQ);
            #pragma unroll
            for (int c = 0; c < 5; c++) {
                double2 p = Mb2[c];
                M_r[i][2 * c]     = d2l(p.x);
                M_r[i][2 * c + 1] = d2l(p.y);
            }
        }
    }
    if (tid < VQ * GQ) {                    // r0 into z_s and h_t
        int gg = tid & 3, v = tid >> 2;
        z_s[(IQ + v) * GQ + gg] = r_bias[v];
        h_t[gg * HTS + 100 + v] = r_bias[v];
    }
    if (tid < IQ * GQ) {                    // x_0
        int gg = tid / IQ, i = tid - gg * IQ;
        z_s[i * GQ + gg] = x[(b0 + gg) * TQ * IQ + i];
    }
    if (tid < 12) {                         // zero pads: z_s j=29..31
        int j = 29 + (tid >> 2), gg = tid & 3;
        z_s[j * GQ + gg] = 0.f;
    }
    if (tid < 32) {                         // zero pads: h_t[g][120..127]
        int gg = tid >> 3;
        h_t[gg * HTS + 120 + (tid & 7)] = 0.f;
    }
    __syncthreads();

    for (int t = 0; t < TQ; t++) {
        // ---- P1: controller h = tanh([x,r] @ Wc + bc)  (packed, 4 accums) ----
        if (tid < CQ) {
            const float4*  wp = (const float4*)Wc4_g + tid;
            const double2* z2 = (const double2*)z_s;
            ull a01 = pk2(bcv), a23 = a01, b01 = 0ull, b23 = 0ull;
            #pragma unroll
            for (int jb = 0; jb < 8; jb += 2) {
                float4 w = wp[jb * CQ];
                double2 za = z2[4*jb+0], zb = z2[4*jb+1], zc = z2[4*jb+2], zd = z2[4*jb+3];
                ull wx = pk2(w.x), wy = pk2(w.y), wz = pk2(w.z), ww = pk2(w.w);
                a01 = ffma2(wx, d2l(za.x), a01); a23 = ffma2(wx, d2l(za.y), a23);
                a01 = ffma2(wy, d2l(zb.x), a01); a23 = ffma2(wy, d2l(zb.y), a23);
                a01 = ffma2(wz, d2l(zc.x), a01); a23 = ffma2(wz, d2l(zc.y), a23);
                a01 = ffma2(ww, d2l(zd.x), a01); a23 = ffma2(ww, d2l(zd.y), a23);
                float4 v = wp[(jb + 1) * CQ];
                double2 ze = z2[4*jb+4], zf = z2[4*jb+5], zg = z2[4*jb+6], zh = z2[4*jb+7];
                ull vx = pk2(v.x), vy = pk2(v.y), vz = pk2(v.z), vw = pk2(v.w);
                b01 = ffma2(vx, d2l(ze.x), b01); b23 = ffma2(vx, d2l(ze.y), b23);
                b01 = ffma2(vy, d2l(zf.x), b01); b23 = ffma2(vy, d2l(zf.y), b23);
                b01 = ffma2(vz, d2l(zg.x), b01); b23 = ffma2(vz, d2l(zg.y), b23);
                b01 = ffma2(vw, d2l(zh.x), b01); b23 = ffma2(vw, d2l(zh.y), b23);
            }
            a01 = fadd2(a01, b01); a23 = fadd2(a23, b23);
            float2 lo = upk2(a01), hi = upk2(a23);
            float h0 = ftanh_(lo.x), h1 = ftanh_(lo.y), h2 = ftanh_(hi.x), h3 = ftanh_(hi.y);
            *(float4*)&h_s[tid * GQ] = make_float4(h0, h1, h2, h3);
            h_t[0 * HTS + tid] = h0; h_t[1 * HTS + tid] = h1;
            h_t[2 * HTS + tid] = h2; h_t[3 * HTS + tid] = h3;
        }
        __syncthreads();

        // ---- P2: head matvecs (packed, 4 accums) + fused activations ----
        if (tid < 92) {
            const double2* h2 = (const double2*)h_s;
            ull a01 = pk2(bsv), a23 = a01, b01 = 0ull, b23 = 0ull;
            #pragma unroll 4
            for (int jb = 0; jb < 24; jb += 2) {
                float4 w = Wp4[jb * od];
                double2 ha = h2[4*jb+0], hb = h2[4*jb+1], hc = h2[4*jb+2], hd = h2[4*jb+3];
                ull wx = pk2(w.x), wy = pk2(w.y), wz = pk2(w.z), ww = pk2(w.w);
                a01 = ffma2(wx, d2l(ha.x), a01); a23 = ffma2(wx, d2l(ha.y), a23);
                a01 = ffma2(wy, d2l(hb.x), a01); a23 = ffma2(wy, d2l(hb.y), a23);
                a01 = ffma2(wz, d2l(hc.x), a01); a23 = ffma2(wz, d2l(hc.y), a23);
                a01 = ffma2(ww, d2l(hd.x), a01); a23 = ffma2(ww, d2l(hd.y), a23);
                float4 v = Wp4[(jb + 1) * od];
                double2 he = h2[4*jb+4], hf = h2[4*jb+5], hg = h2[4*jb+6], hh = h2[4*jb+7];
                ull vx = pk2(v.x), vy = pk2(v.y), vz = pk2(v.z), vw = pk2(v.w);
                b01 = ffma2(vx, d2l(he.x), b01); b23 = ffma2(vx, d2l(he.y), b23);
                b01 = ffma2(vy, d2l(hf.x), b01); b23 = ffma2(vy, d2l(hf.y), b23);
                b01 = ffma2(vz, d2l(hg.x), b01); b23 = ffma2(vz, d2l(hg.y), b23);
                b01 = ffma2(vw, d2l(hh.x), b01); b23 = ffma2(vw, d2l(hh.y), b23);
            }
            {   // jb = 24 (tail)
                float4 w = Wp4[24 * od];
                double2 ha = h2[96], hb = h2[97], hc = h2[98], hd = h2[99];
                ull wx = pk2(w.x), wy = pk2(w.y), wz = pk2(w.z), ww = pk2(w.w);
                a01 = ffma2(wx, d2l(ha.x), a01); a23 = ffma2(wx, d2l(ha.y), a23);
                a01 = ffma2(wy, d2l(hb.x), a01); a23 = ffma2(wy, d2l(hb.y), a23);
                a01 = ffma2(wz, d2l(hc.x), a01); a23 = ffma2(wz, d2l(hc.y), a23);
                a01 = ffma2(ww, d2l(hd.x), a01); a23 = ffma2(ww, d2l(hd.y), a23);
            }
            a01 = fadd2(a01, b01); a23 = fadd2(a23, b23);
            float2 lo = upk2(a01), hi = upk2(a23);
            p_s[0 * PBLK + st] = apply_act(at, lo.x);
            p_s[1 * PBLK + st] = apply_act(at, lo.y);
            p_s[2 * PBLK + st] = apply_act(at, hi.x);
            p_s[3 * PBLK + st] = apply_act(at, hi.y);
        }
        __syncthreads();

        // ======== warp-local phases (batch g); M in registers ========
        float4 srv = *(const float4*)(pg + 20);
        float4 bv  = *(const float4*)(pg + 24);
        float4 swv = *(const float4*)(pg + 28);
        float sr_i = __fdividef(1.f, srv.x + srv.y + srv.z);
        float s_r0 = srv.x * sr_i, s_r1 = srv.y * sr_i, s_r2 = srv.z * sr_i;
        float sw_i = __fdividef(1.f, swv.x + swv.y + swv.z);
        float s_w0 = swv.x * sw_i, s_w1 = swv.y * sw_i, s_w2 = swv.z * sw_i;

        // ---- C1: content addressing (packed dots against register M) ----
        ull drp[4] = {0,0,0,0}, dwp[4] = {0,0,0,0}, n2p[4] = {0,0,0,0};
        ull kr2p = 0ull, kw2p = 0ull;
        const double2* krp = (const double2*)pg;
        const double2* kwp = (const double2*)(pg + 32);
        #pragma unroll
        for (int c = 0; c < 5; c++) {
            double2 krd = krp[c], kwd = kwp[c];
            ull kr01 = d2l(krd.x), kr23 = d2l(krd.y);
            ull kw01 = d2l(kwd.x), kw23 = d2l(kwd.y);
            kr2p = ffma2(kr01, kr01, kr2p); kr2p = ffma2(kr23, kr23, kr2p);
            kw2p = ffma2(kw01, kw01, kw2p); kw2p = ffma2(kw23, kw23, kw2p);
            #pragma unroll
            for (int i = 0; i < 4; i++) {
                ull m01 = M_r[i][2*c], m23 = M_r[i][2*c+1];
                drp[i] = ffma2(kr01, m01, drp[i]); drp[i] = ffma2(kr23, m23, drp[i]);
                dwp[i] = ffma2(kw01, m01, dwp[i]); dwp[i] = ffma2(kw23, m23, dwp[i]);
                n2p[i] = ffma2(m01, m01, n2p[i]);  n2p[i] = ffma2(m23, m23, n2p[i]);
            }
        }
        float2 krt = upk2(kr2p), kwt = upk2(kw2p);
        float knr = sqrtf(krt.x + krt.y), knw = sqrtf(kwt.x + kwt.y);
        float er_r[4], ew_r[4], ser = 0.f, sew = 0.f;
        #pragma unroll
        for (int i = 0; i < 4; i++) {
            float2 dt = upk2(drp[i]), wt2 = upk2(dwp[i]), nt = upk2(n2p[i]);
            float mn = sqrtf(nt.x + nt.y);
            er_r[i] = __expf(bv.x * __fdividef(dt.x + dt.y, knr * mn + EPSQ));
            ew_r[i] = __expf(bv.z * __fdividef(wt2.x + wt2.y, knw * mn + EPSQ));
            ser += er_r[i]; sew += ew_r[i];
        }
        ser = warp_sum(ser); sew = warp_sum(sew);

        // ---- C2: read-head interp + conv via shfl + sharpen ----
        float ginv = bv.y * __fdividef(1.f, ser);
        float omg  = 1.f - bv.y;
        float wg_r[4];
        #pragma unroll
        for (int i = 0; i < 4; i++)
            wg_r[i] = fmaf(ginv, er_r[i], omg * wprev_r[i]);
        float wpr_r[4], ssp = 0.f;
        #pragma unroll
        for (int i = 0; i < 4; i++) {
            float tnp = (lane == 0)  ? wg_r[(i + 1) & 3] : wg_r[i];
            float tnm = (lane == 31) ? wg_r[(i + 3) & 3] : wg_r[i];
            float w_p = __shfl_sync(0xffffffffu, tnp, (lane + 1)  & 31);
            float w_m = __shfl_sync(0xffffffffu, tnm, (lane + 31) & 31);
            float ws  = s_r0 * w_p + s_r1 * wg_r[i] + s_r2 * w_m;
            wpr_r[i]  = __expf(srv.w * __logf(ws));
            ssp += wpr_r[i];
        }
        float sp = warp_sum(ssp);
        float invsp = __fdividef(1.f, sp + EPSQ);

        // ---- C3: write-head interp + conv via shfl + sharpen ----
        float gwinv = bv.w * __fdividef(1.f, sew);
        float omgsp = (1.f - bv.w) * invsp;
        float wt_r[4];
        #pragma unroll
        for (int i = 0; i < 4; i++)
            wt_r[i] = fmaf(gwinv, ew_r[i], omgsp * wpr_r[i]);
        float wpw_r[4], swp = 0.f;
        #pragma unroll
        for (int i = 0; i < 4; i++) {
            float tnp = (lane == 0)  ? wt_r[(i + 1) & 3] : wt_r[i];
            float tnm = (lane == 31) ? wt_r[(i + 3) & 3] : wt_r[i];
            float w_p = __shfl_sync(0xffffffffu, tnp, (lane + 1)  & 31);
            float w_m = __shfl_sync(0xffffffffu, tnm, (lane + 31) & 31);
            float ws  = s_w0 * w_p + s_w1 * wt_r[i] + s_w2 * w_m;
            wpw_r[i]  = __expf(swv.w * __logf(ws));
            swp += wpw_r[i];
        }
        float spw = warp_sum(swp);
        float invspw = __fdividef(1.f, spw + EPSQ);
        #pragma unroll
        for (int i = 0; i < 4; i++)
            wprev_r[i] = wpw_r[i] * invspw;

        // ---- C4: fused r-readout + M update entirely in registers ----
        ull wr_d[4], ww_d[4], nww_d[4];
        #pragma unroll
        for (int i = 0; i < 4; i++) {
            wr_d[i]  = pk2(wpr_r[i] * invsp);
            ww_d[i]  = pk2(wprev_r[i]);
            nww_d[i] = pk2(-wprev_r[i]);
        }
        ull r01[5], r23[5];
        #pragma unroll
        for (int c = 0; c < 5; c++) {
            double2 ed = ((const double2*)(pg + 52))[c];
            double2 ad = ((const double2*)(pg + 72))[c];
            ull e01 = d2l(ed.x), e23 = d2l(ed.y);
            ull a01 = d2l(ad.x), a23 = d2l(ad.y);
            ull acc01 = 0ull, acc23 = 0ull;
            #pragma unroll
            for (int i = 0; i < 4; i++) {
                ull m01 = M_r[i][2*c], m23 = M_r[i][2*c+1];
                acc01 = ffma2(wr_d[i], m01, acc01);
                acc23 = ffma2(wr_d[i], m23, acc23);
                ull nwe01 = fmul2(nww_d[i], e01), nwe23 = fmul2(nww_d[i], e23);
                m01 = ffma2(nwe01, m01, m01);   m23 = ffma2(nwe23, m23, m23);
                m01 = ffma2(ww_d[i], a01, m01); m23 = ffma2(ww_d[i], a23, m23);
                M_r[i][2*c] = m01; M_r[i][2*c+1] = m23;
            }
            r01[c] = warp_sum2(acc01);
            r23[c] = warp_sum2(acc23);
        }
        if (lane == 0) {
            #pragma unroll
            for (int c = 0; c < 5; c++) {
                float2 x01 = upk2(r01[c]), x23 = upk2(r23[c]);
                int v = c * 4;
                z_s[(IQ + v + 0) * GQ + g] = x01.x;
                z_s[(IQ + v + 1) * GQ + g] = x01.y;
                z_s[(IQ + v + 2) * GQ + g] = x23.x;
                z_s[(IQ + v + 3) * GQ + g] = x23.y;
                *(float4*)&h_t[g * HTS + 100 + v] =
                    make_float4(x01.x, x01.y, x23.x, x23.y);
            }
        }
        __syncwarp();

        // ---- out = sigmoid([h, r] @ Wf + bf)  (8 outs x 4 partials) ----
        {
            int o = lane & 7, part = lane >> 3;
            const float4* wv  = (const float4*)Wf4_g + o;        // + jb*8
            const float4* hv4 = (const float4*)(h_t + g * HTS);  // + jb
            float acc = 0.f;
            #pragma unroll
            for (int jl = 0; jl < 8; jl++) {
                int jb = part * 8 + jl;
                float4 w = wv[jb * OQ];
                float4 h = hv4[jb];
                acc = fmaf(w.x, h.x, fmaf(w.y, h.y, fmaf(w.z, h.z, fmaf(w.w, h.w, acc))));
            }
            acc += __shfl_xor_sync(0xffffffffu, acc, 8);
            acc += __shfl_xor_sync(0xffffffffu, acc, 16);
            if (lane < 8)
                out[((b0 + g) * TQ + t) * OQ + o] = fsigmoid_(acc + bfv);
        }
        // prefetch next x_t
        if (t + 1 < TQ && tid < IQ * GQ) {
            int gg = tid / IQ, i = tid - gg * IQ;
            z_s[i * GQ + gg] = x[((b0 + gg) * TQ + (t + 1)) * IQ + i];
        }
        __syncthreads();
    }
}

extern "C" void kernel_launch(void* const* d_in, const int* in_sizes, int n_in,
                              void* d_out, int out_size) {
    const float* x      = (const float*)d_in[0];
    const float* Wc     = (const float*)d_in[1];
    const float* bc     = (const float*)d_in[2];
    const float* Wr     = (const float*)d_in[3];
    const float* br     = (const float*)d_in[4];
    const float* Ww     = (const float*)d_in[5];
    const float* bw     = (const float*)d_in[6];
    const float* Wf     = (const float*)d_in[7];
    const float* bf     = (const float*)d_in[8];
    const float* r_bias = (const float*)d_in[9];
    const float* M_bias = (const float*)d_in[10];

    int B = in_sizes[0] / (TQ * IQ);        // 2048
    int grid = B / GQ;                      // 512

    prep_kernel<<<65, 256>>>(Wc, Wr, Ww, Wf);   // 16496 elements

    size_t smem = (size_t)(32 * GQ + CQ * GQ + GQ * PBLK + GQ * HTS)
                  * sizeof(float);          // 5696 B
    cudaFuncSetAttribute(ntm_kernel, cudaFuncAttributeMaxDynamicSharedMemorySize, (int)smem);

    ntm_kernel<<<grid, BLK, smem>>>(x, bc, br, bw, bf, r_bias, M_bias, (float*)d_out);
}

// round 14
// speedup vs baseline: 1.0988x; 1.0988x over previous
#include <cuda_runtime.h>
#include <math.h>

#define TQ 64
#define IQ 9
#define NQ 128
#define VQ 20
#define CQ 100
#define OQ 8
#define GQ 4
#define BLK 128
#define EPSQ 1e-8f
#define PBLK 96
#define HTS 128   // h_t row: h(100) | r(20) | zero pad(8)

// p_s per-g block (96 floats), vector-aligned:
//  0..19 kr | 20..22 sr, 23 gammar | 24 betar, 25 gr, 26 betaw, 27 gw
//  28..30 sw, 31 gammaw | 32..51 kw | 52..71 e | 72..91 a | 92..95 pad

// 4-j interleaved weights: W4[jb][col][q] = W[(4jb+q)*od + col]
__device__ __align__(16) float Wc4_g[8 * CQ * 4];    // 3200 (j padded 29->32)
__device__ __align__(16) float Wr4_g[25 * 26 * 4];   // 2600
__device__ __align__(16) float Ww4_g[25 * 66 * 4];   // 6600
__device__ __align__(16) float Wf4_g[32 * OQ * 4];   // 4096 (j padded 120->128)

__global__ void prep_kernel(const float* __restrict__ Wc, const float* __restrict__ Wr,
                            const float* __restrict__ Ww, const float* __restrict__ Wf) {
    int i = blockIdx.x * blockDim.x + threadIdx.x;
    if (i < 3200) {
        int jb = i / 400, rem = i % 400, c = rem >> 2, q = rem & 3, j = jb * 4 + q;
        Wc4_g[i] = (j < 29) ? Wc[j * CQ + c] : 0.f;
    }
    int j2 = i - 3200;
    if (j2 >= 0 && j2 < 2600) {
        int jb = j2 / 104, rem = j2 % 104, c = rem >> 2, q = rem & 3;
        Wr4_g[j2] = Wr[(jb * 4 + q) * 26 + c];
    }
    int k2 = i - 5800;
    if (k2 >= 0 && k2 < 6600) {
        int jb = k2 / 264, rem = k2 % 264, c = rem >> 2, q = rem & 3;
        Ww4_g[k2] = Ww[(jb * 4 + q) * 66 + c];
    }
    int l2 = i - 12400;
    if (l2 >= 0 && l2 < 4096) {
        int jb = l2 / 32, rem = l2 % 32, o = rem >> 2, q = rem & 3, j = jb * 4 + q;
        Wf4_g[l2] = (j < 120) ? Wf[j * OQ + o] : 0.f;
    }
}

typedef unsigned long long ull;
__device__ __forceinline__ ull pk2(float v) {
    ull r; asm("mov.b64 %0, {%1, %1};" : "=l"(r) : "f"(v)); return r;
}
__device__ __forceinline__ float2 upk2(ull v) {
    float2 r; asm("mov.b64 {%0, %1}, %2;" : "=f"(r.x), "=f"(r.y) : "l"(v)); return r;
}
__device__ __forceinline__ ull ffma2(ull a, ull b, ull c) {
    ull d; asm("fma.rn.f32x2 %0, %1, %2, %3;" : "=l"(d) : "l"(a), "l"(b), "l"(c)); return d;
}
__device__ __forceinline__ ull fmul2(ull a, ull b) {
    ull d; asm("mul.rn.f32x2 %0, %1, %2;" : "=l"(d) : "l"(a), "l"(b)); return d;
}
__device__ __forceinline__ ull fadd2(ull a, ull b) {
    ull d; asm("add.rn.f32x2 %0, %1, %2;" : "=l"(d) : "l"(a), "l"(b)); return d;
}
__device__ __forceinline__ ull d2l(double v) { return __double_as_longlong(v); }
__device__ __forceinline__ double l2d(ull v) { return __longlong_as_double(v); }

__device__ __forceinline__ float ftanh_(float x) {
    float xc = fminf(fmaxf(x, -15.f), 15.f);
    float e = __expf(2.f * xc);
    return __fdividef(e - 1.f, e + 1.f);
}
__device__ __forceinline__ float fsoftplus_(float x) {
    return fmaxf(x, 0.f) + __logf(1.f + __expf(-fabsf(x)));
}
__device__ __forceinline__ float fsigmoid_(float x) {
    return __fdividef(1.f, 1.f + __expf(-x));
}
__device__ __forceinline__ float apply_act(int at, float v) {
    switch (at) {
        case 0:  return ftanh_(v);
        case 1:  return fsoftplus_(v);
        case 2:  return fsigmoid_(v);
        case 3:  return __expf(v);
        default: return 1.f + fsoftplus_(v);
    }
}
__device__ __forceinline__ float warp_sum(float v) {
    v += __shfl_xor_sync(0xffffffffu, v, 16);
    v += __shfl_xor_sync(0xffffffffu, v, 8);
    v += __shfl_xor_sync(0xffffffffu, v, 4);
    v += __shfl_xor_sync(0xffffffffu, v, 2);
    v += __shfl_xor_sync(0xffffffffu, v, 1);
    return v;
}
__device__ __forceinline__ ull warp_sum2(ull v) {
    #pragma unroll
    for (int k = 16; k; k >>= 1) {
        ull o = __shfl_xor_sync(0xffffffffu, v, k);
        asm("add.rn.f32x2 %0, %0, %1;" : "+l"(v) : "l"(o));
    }
    return v;
}

__global__ __launch_bounds__(BLK, 4) void ntm_kernel(
    const float* __restrict__ x,
    const float* __restrict__ bc, const float* __restrict__ br,
    const float* __restrict__ bw, const float* __restrict__ bf,
    const float* __restrict__ r_bias, const float* __restrict__ M_bias,
    float* __restrict__ out)
{
    extern __shared__ float sm[];
    float* M_s = sm;                        // [G][128][20] 10240 (80B rows)
    float* z_s = M_s + GQ * NQ * VQ;        // [32][G]  controller input (x|r|pad)
    float* h_s = z_s + 32 * GQ;             // [100][G] controller hidden
    float* p_s = h_s + CQ * GQ;             // [G][96]  head params
    float* h_t = p_s + GQ * PBLK;           // [G][128] [h|r|pad] per-g contiguous

    const int tid  = threadIdx.x;
    const int lane = tid & 31;
    const int g    = tid >> 5;              // warp == batch element
    const int b0   = blockIdx.x * GQ;

    // ---- hoisted per-thread constants ----
    float bcv = (tid < CQ) ? bc[tid] : 0.f;
    const float4* Wp4 = (const float4*)Ww4_g;
    int od = 66, st = 0, at = 0; float bsv = 0.f;
    {
        bool rh = (tid < 26);
        int c = rh ? tid : tid - 26;
        if (rh)            { Wp4 = (const float4*)Wr4_g + c; od = 26; bsv = br[c]; }
        else if (tid < 92) { Wp4 = (const float4*)Ww4_g + c; bsv = bw[c]; }
        if      (c < 20)  { st = (rh ? 0 : 32) + c;       at = 0; }
        else if (c == 20) { st = rh ? 24 : 26;            at = 1; }
        else if (c == 21) { st = rh ? 25 : 27;            at = 2; }
        else if (c < 25)  { st = (rh ? 20 : 28) + (c-22); at = 3; }
        else if (c == 25) { st = rh ? 23 : 31;            at = 4; }
        else if (c < 46)  { st = 52 + (c - 26);           at = 2; }
        else              { st = 72 + (c - 46);           at = 0; }
    }
    float bfv = bf[lane & 7];
    const float* pg = p_s + g * PBLK;

    // ---- init state: lane owns rows lane+32i of batch g ----
    float wprev_r[GQ];
    {
        const float4* Mb = (const float4*)M_bias;
        #pragma unroll
        for (int i = 0; i < GQ; i++) {
            int n = lane + 32 * i;
            wprev_r[i] = 0.f;
            float4* Mr = (float4*)&M_s[(g * NQ + n) * VQ];
            #pragma unroll
            for (int c2 = 0; c2 < 5; c2++) Mr[c2] = Mb[n * 5 + c2];
        }
    }
    if (tid < VQ * GQ) {                    // r0 into z_s and h_t
        int gg = tid & 3, v = tid >> 2;
        z_s[(IQ + v) * GQ + gg] = r_bias[v];
        h_t[gg * HTS + 100 + v] = r_bias[v];
    }
    if (tid < IQ * GQ) {                    // x_0
        int gg = tid / IQ, i = tid - gg * IQ;
        z_s[i * GQ + gg] = x[(b0 + gg) * TQ * IQ + i];
    }
    if (tid < 12) {                         // zero pads: z_s j=29..31
        int j = 29 + (tid >> 2), gg = tid & 3;
        z_s[j * GQ + gg] = 0.f;
    }
    if (tid < 32) {                         // zero pads: h_t[g][120..127]
        int gg = tid >> 3;
        h_t[gg * HTS + 120 + (tid & 7)] = 0.f;
    }
    __syncthreads();

    for (int t = 0; t < TQ; t++) {
        // ---- P1: controller h = tanh([x,r] @ Wc + bc)  (packed, dual accums) ----
        if (tid < CQ) {
            const float4*  wp = (const float4*)Wc4_g + tid;
            const double2* z2 = (const double2*)z_s;
            ull a01 = pk2(bcv), a23 = a01, b01 = 0ull, b23 = 0ull;
            #pragma unroll
            for (int jb = 0; jb < 8; jb += 2) {
                float4 w = wp[jb * CQ];
                double2 za = z2[4*jb+0], zb = z2[4*jb+1], zc = z2[4*jb+2], zd = z2[4*jb+3];
                ull wx = pk2(w.x), wy = pk2(w.y), wz = pk2(w.z), ww = pk2(w.w);
                a01 = ffma2(wx, d2l(za.x), a01); a23 = ffma2(wx, d2l(za.y), a23);
                a01 = ffma2(wy, d2l(zb.x), a01); a23 = ffma2(wy, d2l(zb.y), a23);
                a01 = ffma2(wz, d2l(zc.x), a01); a23 = ffma2(wz, d2l(zc.y), a23);
                a01 = ffma2(ww, d2l(zd.x), a01); a23 = ffma2(ww, d2l(zd.y), a23);
                float4 v = wp[(jb + 1) * CQ];
                double2 ze = z2[4*jb+4], zf = z2[4*jb+5], zg = z2[4*jb+6], zh = z2[4*jb+7];
                ull vx = pk2(v.x), vy = pk2(v.y), vz = pk2(v.z), vw = pk2(v.w);
                b01 = ffma2(vx, d2l(ze.x), b01); b23 = ffma2(vx, d2l(ze.y), b23);
                b01 = ffma2(vy, d2l(zf.x), b01); b23 = ffma2(vy, d2l(zf.y), b23);
                b01 = ffma2(vz, d2l(zg.x), b01); b23 = ffma2(vz, d2l(zg.y), b23);
                b01 = ffma2(vw, d2l(zh.x), b01); b23 = ffma2(vw, d2l(zh.y), b23);
            }
            a01 = fadd2(a01, b01); a23 = fadd2(a23, b23);
            float2 lo = upk2(a01), hi = upk2(a23);
            float h0 = ftanh_(lo.x), h1 = ftanh_(lo.y), h2 = ftanh_(hi.x), h3 = ftanh_(hi.y);
            *(float4*)&h_s[tid * GQ] = make_float4(h0, h1, h2, h3);
            h_t[0 * HTS + tid] = h0; h_t[1 * HTS + tid] = h1;
            h_t[2 * HTS + tid] = h2; h_t[3 * HTS + tid] = h3;
        }
        __syncthreads();

        // ---- P2: head matvecs (packed, dual accums) + fused activations ----
        if (tid < 92) {
            const double2* h2 = (const double2*)h_s;
            ull a01 = pk2(bsv), a23 = a01, b01 = 0ull, b23 = 0ull;
            #pragma unroll 4
            for (int jb = 0; jb < 24; jb += 2) {
                float4 w = Wp4[jb * od];
                double2 ha = h2[4*jb+0], hb = h2[4*jb+1], hc = h2[4*jb+2], hd = h2[4*jb+3];
                ull wx = pk2(w.x), wy = pk2(w.y), wz = pk2(w.z), ww = pk2(w.w);
                a01 = ffma2(wx, d2l(ha.x), a01); a23 = ffma2(wx, d2l(ha.y), a23);
                a01 = ffma2(wy, d2l(hb.x), a01); a23 = ffma2(wy, d2l(hb.y), a23);
                a01 = ffma2(wz, d2l(hc.x), a01); a23 = ffma2(wz, d2l(hc.y), a23);
                a01 = ffma2(ww, d2l(hd.x), a01); a23 = ffma2(ww, d2l(hd.y), a23);
                float4 v = Wp4[(jb + 1) * od];
                double2 he = h2[4*jb+4], hf = h2[4*jb+5], hg = h2[4*jb+6], hh = h2[4*jb+7];
                ull vx = pk2(v.x), vy = pk2(v.y), vz = pk2(v.z), vw = pk2(v.w);
                b01 = ffma2(vx, d2l(he.x), b01); b23 = ffma2(vx, d2l(he.y), b23);
                b01 = ffma2(vy, d2l(hf.x), b01); b23 = ffma2(vy, d2l(hf.y), b23);
                b01 = ffma2(vz, d2l(hg.x), b01); b23 = ffma2(vz, d2l(hg.y), b23);
                b01 = ffma2(vw, d2l(hh.x), b01); b23 = ffma2(vw, d2l(hh.y), b23);
            }
            {   // jb = 24 tail
                float4 w = Wp4[24 * od];
                double2 ha = h2[96], hb = h2[97], hc = h2[98], hd = h2[99];
                ull wx = pk2(w.x), wy = pk2(w.y), wz = pk2(w.z), ww = pk2(w.w);
                a01 = ffma2(wx, d2l(ha.x), a01); a23 = ffma2(wx, d2l(ha.y), a23);
                a01 = ffma2(wy, d2l(hb.x), a01); a23 = ffma2(wy, d2l(hb.y), a23);
                a01 = ffma2(wz, d2l(hc.x), a01); a23 = ffma2(wz, d2l(hc.y), a23);
                a01 = ffma2(ww, d2l(hd.x), a01); a23 = ffma2(ww, d2l(hd.y), a23);
            }
            a01 = fadd2(a01, b01); a23 = fadd2(a23, b23);
            float2 lo = upk2(a01), hi = upk2(a23);
            p_s[0 * PBLK + st] = apply_act(at, lo.x);
            p_s[1 * PBLK + st] = apply_act(at, lo.y);
            p_s[2 * PBLK + st] = apply_act(at, hi.x);
            p_s[3 * PBLK + st] = apply_act(at, hi.y);
        }
        __syncthreads();

        // ======== warp-local phases (batch g); M in SMEM ========
        float4 srv = *(const float4*)(pg + 20);
        float4 bv  = *(const float4*)(pg + 24);
        float4 swv = *(const float4*)(pg + 28);
        float sr_i = __fdividef(1.f, srv.x + srv.y + srv.z);
        float s_r0 = srv.x * sr_i, s_r1 = srv.y * sr_i, s_r2 = srv.z * sr_i;
        float sw_i = __fdividef(1.f, swv.x + swv.y + swv.z);
        float s_w0 = swv.x * sw_i, s_w1 = swv.y * sw_i, s_w2 = swv.z * sw_i;

        // ---- C1: content addressing (packed dots, M loaded as double2) ----
        ull drp[4] = {0,0,0,0}, dwp[4] = {0,0,0,0}, n2p[4] = {0,0,0,0};
        ull kr2p = 0ull, kw2p = 0ull;
        const double2* krp = (const double2*)pg;
        const double2* kwp = (const double2*)(pg + 32);
        #pragma unroll
        for (int c = 0; c < 5; c++) {
            double2 krd = krp[c], kwd = kwp[c];
            ull kr01 = d2l(krd.x), kr23 = d2l(krd.y);
            ull kw01 = d2l(kwd.x), kw23 = d2l(kwd.y);
            kr2p = ffma2(kr01, kr01, kr2p); kr2p = ffma2(kr23, kr23, kr2p);
            kw2p = ffma2(kw01, kw01, kw2p); kw2p = ffma2(kw23, kw23, kw2p);
            #pragma unroll
            for (int i = 0; i < 4; i++) {
                double2 md = *(const double2*)&M_s[(g * NQ + lane + 32 * i) * VQ + c * 4];
                ull m01 = d2l(md.x), m23 = d2l(md.y);
                drp[i] = ffma2(kr01, m01, drp[i]); drp[i] = ffma2(kr23, m23, drp[i]);
                dwp[i] = ffma2(kw01, m01, dwp[i]); dwp[i] = ffma2(kw23, m23, dwp[i]);
                n2p[i] = ffma2(m01, m01, n2p[i]);  n2p[i] = ffma2(m23, m23, n2p[i]);
            }
        }
        float2 krt = upk2(kr2p), kwt = upk2(kw2p);
        float knr = sqrtf(krt.x + krt.y), knw = sqrtf(kwt.x + kwt.y);
        float er_r[4], ew_r[4], ser = 0.f, sew = 0.f;
        #pragma unroll
        for (int i = 0; i < 4; i++) {
            float2 dt = upk2(drp[i]), wt2 = upk2(dwp[i]), nt = upk2(n2p[i]);
            float mn = sqrtf(nt.x + nt.y);
            er_r[i] = __expf(bv.x * __fdividef(dt.x + dt.y, knr * mn + EPSQ));
            ew_r[i] = __expf(bv.z * __fdividef(wt2.x + wt2.y, knw * mn + EPSQ));
            ser += er_r[i]; sew += ew_r[i];
        }
        ser = warp_sum(ser); sew = warp_sum(sew);

        // ---- C2: read-head interp + conv via shfl + sharpen ----
        float ginv = bv.y * __fdividef(1.f, ser);
        float omg  = 1.f - bv.y;
        float wg_r[4];
        #pragma unroll
        for (int i = 0; i < 4; i++)
            wg_r[i] = fmaf(ginv, er_r[i], omg * wprev_r[i]);
        float wpr_r[4], ssp = 0.f;
        #pragma unroll
        for (int i = 0; i < 4; i++) {
            float tnp = (lane == 0)  ? wg_r[(i + 1) & 3] : wg_r[i];
            float tnm = (lane == 31) ? wg_r[(i + 3) & 3] : wg_r[i];
            float w_p = __shfl_sync(0xffffffffu, tnp, (lane + 1)  & 31);
            float w_m = __shfl_sync(0xffffffffu, tnm, (lane + 31) & 31);
            float ws  = s_r0 * w_p + s_r1 * wg_r[i] + s_r2 * w_m;
            wpr_r[i]  = __expf(srv.w * __logf(ws));
            ssp += wpr_r[i];
        }
        float sp = warp_sum(ssp);
        float invsp = __fdividef(1.f, sp + EPSQ);

        // ---- C3: write-head interp + conv via shfl + sharpen ----
        float gwinv = bv.w * __fdividef(1.f, sew);
        float omgsp = (1.f - bv.w) * invsp;
        float wt_r[4];
        #pragma unroll
        for (int i = 0; i < 4; i++)
            wt_r[i] = fmaf(gwinv, ew_r[i], omgsp * wpr_r[i]);
        float wpw_r[4], swp = 0.f;
        #pragma unroll
        for (int i = 0; i < 4; i++) {
            float tnp = (lane == 0)  ? wt_r[(i + 1) & 3] : wt_r[i];
            float tnm = (lane == 31) ? wt_r[(i + 3) & 3] : wt_r[i];
            float w_p = __shfl_sync(0xffffffffu, tnp, (lane + 1)  & 31);
            float w_m = __shfl_sync(0xffffffffu, tnm, (lane + 31) & 31);
            float ws  = s_w0 * w_p + s_w1 * wt_r[i] + s_w2 * w_m;
            wpw_r[i]  = __expf(swv.w * __logf(ws));
            swp += wpw_r[i];
        }
        float spw = warp_sum(swp);
        float invspw = __fdividef(1.f, spw + EPSQ);
        #pragma unroll
        for (int i = 0; i < 4; i++)
            wprev_r[i] = wpw_r[i] * invspw;

        // ---- C4: fused r-readout + M update (packed, M in SMEM) ----
        ull wr_d[4], ww_d[4], nww_d[4];
        #pragma unroll
        for (int i = 0; i < 4; i++) {
            wr_d[i]  = pk2(wpr_r[i] * invsp);
            ww_d[i]  = pk2(wprev_r[i]);
            nww_d[i] = pk2(-wprev_r[i]);
        }
        ull r01[5], r23[5];
        #pragma unroll
        for (int c = 0; c < 5; c++) {
            double2 ed = ((const double2*)(pg + 52))[c];
            double2 ad = ((const double2*)(pg + 72))[c];
            ull e01 = d2l(ed.x), e23 = d2l(ed.y);
            ull a01 = d2l(ad.x), a23 = d2l(ad.y);
            ull acc01 = 0ull, acc23 = 0ull;
            #pragma unroll
            for (int i = 0; i < 4; i++) {
                double2* mp = (double2*)&M_s[(g * NQ + lane + 32 * i) * VQ + c * 4];
                double2 md = *mp;
                ull m01 = d2l(md.x), m23 = d2l(md.y);
                acc01 = ffma2(wr_d[i], m01, acc01);
                acc23 = ffma2(wr_d[i], m23, acc23);
                ull nwe01 = fmul2(nww_d[i], e01), nwe23 = fmul2(nww_d[i], e23);
                m01 = ffma2(nwe01, m01, m01);   m23 = ffma2(nwe23, m23, m23);
                m01 = ffma2(ww_d[i], a01, m01); m23 = ffma2(ww_d[i], a23, m23);
                md.x = l2d(m01); md.y = l2d(m23);
                *mp = md;
            }
            r01[c] = warp_sum2(acc01);
            r23[c] = warp_sum2(acc23);
        }
        if (lane == 0) {
            #pragma unroll
            for (int c = 0; c < 5; c++) {
                float2 x01 = upk2(r01[c]), x23 = upk2(r23[c]);
                int v = c * 4;
                z_s[(IQ + v + 0) * GQ + g] = x01.x;
                z_s[(IQ + v + 1) * GQ + g] = x01.y;
                z_s[(IQ + v + 2) * GQ + g] = x23.x;
                z_s[(IQ + v + 3) * GQ + g] = x23.y;
                *(float4*)&h_t[g * HTS + 100 + v] =
                    make_float4(x01.x, x01.y, x23.x, x23.y);
            }
        }
        __syncwarp();

        // ---- out = sigmoid([h, r] @ Wf + bf)  (8 outs x 4 partials) ----
        {
            int o = lane & 7, part = lane >> 3;
            const float4* wv  = (const float4*)Wf4_g + o;        // + jb*8
            const float4* hv4 = (const float4*)(h_t + g * HTS);  // + jb
            float acc = 0.f;
            #pragma unroll
            for (int jl = 0; jl < 8; jl++) {
                int jb = part * 8 + jl;
                float4 w = wv[jb * OQ];
                float4 h = hv4[jb];
                acc = fmaf(w.x, h.x, fmaf(w.y, h.y, fmaf(w.z, h.z, fmaf(w.w, h.w, acc))));
            }
            acc += __shfl_xor_sync(0xffffffffu, acc, 8);
            acc += __shfl_xor_sync(0xffffffffu, acc, 16);
            if (lane < 8)
                out[((b0 + g) * TQ + t) * OQ + o] = fsigmoid_(acc + bfv);
        }
        // prefetch next x_t
        if (t + 1 < TQ && tid < IQ * GQ) {
            int gg = tid / IQ, i = tid - gg * IQ;
            z_s[i * GQ + gg] = x[((b0 + gg) * TQ + (t + 1)) * IQ + i];
        }
        __syncthreads();
    }
}

extern "C" void kernel_launch(void* const* d_in, const int* in_sizes, int n_in,
                              void* d_out, int out_size) {
    const float* x      = (const float*)d_in[0];
    const float* Wc     = (const float*)d_in[1];
    const float* bc     = (const float*)d_in[2];
    const float* Wr     = (const float*)d_in[3];
    const float* br     = (const float*)d_in[4];
    const float* Ww     = (const float*)d_in[5];
    const float* bw     = (const float*)d_in[6];
    const float* Wf     = (const float*)d_in[7];
    const float* bf     = (const float*)d_in[8];
    const float* r_bias = (const float*)d_in[9];
    const float* M_bias = (const float*)d_in[10];

    int B = in_sizes[0] / (TQ * IQ);        // 2048
    int grid = B / GQ;                      // 512

    prep_kernel<<<65, 256>>>(Wc, Wr, Ww, Wf);   // 16496 elements

    size_t smem = (size_t)(GQ * NQ * VQ + 32 * GQ + CQ * GQ + GQ * PBLK + GQ * HTS)
                  * sizeof(float);          // 46656 B
    cudaFuncSetAttribute(ntm_kernel, cudaFuncAttributeMaxDynamicSharedMemorySize, (int)smem);

    ntm_kernel<<<grid, BLK, smem>>>(x, bc, br, bw, bf, r_bias, M_bias, (float*)d_out);
}

// round 15
// speedup vs baseline: 1.1252x; 1.0240x over previous
#include <cuda_runtime.h>
#include <math.h>

#define TQ 64
#define IQ 9
#define NQ 128
#define VQ 20
#define CQ 100
#define OQ 8
#define GQ 4
#define BLK 128
#define EPSQ 1e-8f
#define PBLK 96
#define HTS 128   // h_t row: h(100) | r(20) | zero pad(8)

// p_s per-g block (96 floats), vector-aligned:
//  0..19 kr | 20..22 sr, 23 gammar | 24 betar, 25 gr, 26 betaw, 27 gw
//  28..30 sw, 31 gammaw | 32..51 kw | 52..71 e | 72..91 a | 92..95 pad

// 4-j interleaved weights: W4[jb][col][q] = W[(4jb+q)*od + col]
__device__ __align__(16) float Wc4_g[8 * CQ * 4];    // 3200 (j padded 29->32)
__device__ __align__(16) float Wr4_g[25 * 26 * 4];   // 2600
__device__ __align__(16) float Ww4_g[25 * 66 * 4];   // 6600
__device__ __align__(16) float Wf4_g[32 * OQ * 4];   // 4096 (j padded 120->128)

__global__ void prep_kernel(const float* __restrict__ Wc, const float* __restrict__ Wr,
                            const float* __restrict__ Ww, const float* __restrict__ Wf) {
    int i = blockIdx.x * blockDim.x + threadIdx.x;
    if (i < 3200) {
        int jb = i / 400, rem = i % 400, c = rem >> 2, q = rem & 3, j = jb * 4 + q;
        Wc4_g[i] = (j < 29) ? Wc[j * CQ + c] : 0.f;
    }
    int j2 = i - 3200;
    if (j2 >= 0 && j2 < 2600) {
        int jb = j2 / 104, rem = j2 % 104, c = rem >> 2, q = rem & 3;
        Wr4_g[j2] = Wr[(jb * 4 + q) * 26 + c];
    }
    int k2 = i - 5800;
    if (k2 >= 0 && k2 < 6600) {
        int jb = k2 / 264, rem = k2 % 264, c = rem >> 2, q = rem & 3;
        Ww4_g[k2] = Ww[(jb * 4 + q) * 66 + c];
    }
    int l2 = i - 12400;
    if (l2 >= 0 && l2 < 4096) {
        int jb = l2 / 32, rem = l2 % 32, o = rem >> 2, q = rem & 3, j = jb * 4 + q;
        Wf4_g[l2] = (j < 120) ? Wf[j * OQ + o] : 0.f;
    }
}

typedef unsigned long long ull;
__device__ __forceinline__ ull pk2(float v) {
    ull r; asm("mov.b64 %0, {%1, %1};" : "=l"(r) : "f"(v)); return r;
}
__device__ __forceinline__ ull pkf2(float a, float b) {
    ull r; asm("mov.b64 %0, {%1, %2};" : "=l"(r) : "f"(a), "f"(b)); return r;
}
__device__ __forceinline__ float2 upk2(ull v) {
    float2 r; asm("mov.b64 {%0, %1}, %2;" : "=f"(r.x), "=f"(r.y) : "l"(v)); return r;
}
__device__ __forceinline__ ull ffma2(ull a, ull b, ull c) {
    ull d; asm("fma.rn.f32x2 %0, %1, %2, %3;" : "=l"(d) : "l"(a), "l"(b), "l"(c)); return d;
}
__device__ __forceinline__ ull fmul2(ull a, ull b) {
    ull d; asm("mul.rn.f32x2 %0, %1, %2;" : "=l"(d) : "l"(a), "l"(b)); return d;
}
__device__ __forceinline__ ull fadd2(ull a, ull b) {
    ull d; asm("add.rn.f32x2 %0, %1, %2;" : "=l"(d) : "l"(a), "l"(b)); return d;
}
__device__ __forceinline__ ull d2l(double v) { return __double_as_longlong(v); }
__device__ __forceinline__ double l2d(ull v) { return __longlong_as_double(v); }

__device__ __forceinline__ float ftanh_(float x) {
    float xc = fminf(fmaxf(x, -15.f), 15.f);
    float e = __expf(2.f * xc);
    return __fdividef(e - 1.f, e + 1.f);
}
__device__ __forceinline__ float fsoftplus_(float x) {
    return fmaxf(x, 0.f) + __logf(1.f + __expf(-fabsf(x)));
}
__device__ __forceinline__ float fsigmoid_(float x) {
    return __fdividef(1.f, 1.f + __expf(-x));
}
__device__ __forceinline__ float apply_act(int at, float v) {
    switch (at) {
        case 0:  return ftanh_(v);
        case 1:  return fsoftplus_(v);
        case 2:  return fsigmoid_(v);
        case 3:  return __expf(v);
        default: return 1.f + fsoftplus_(v);
    }
}
__device__ __forceinline__ float warp_sum(float v) {
    v += __shfl_xor_sync(0xffffffffu, v, 16);
    v += __shfl_xor_sync(0xffffffffu, v, 8);
    v += __shfl_xor_sync(0xffffffffu, v, 4);
    v += __shfl_xor_sync(0xffffffffu, v, 2);
    v += __shfl_xor_sync(0xffffffffu, v, 1);
    return v;
}
__device__ __forceinline__ ull warp_sum2(ull v) {
    #pragma unroll
    for (int k = 16; k; k >>= 1) {
        ull o = __shfl_xor_sync(0xffffffffu, v, k);
        asm("add.rn.f32x2 %0, %0, %1;" : "+l"(v) : "l"(o));
    }
    return v;
}

__global__ __launch_bounds__(BLK, 4) void ntm_kernel(
    const float* __restrict__ x,
    const float* __restrict__ bc, const float* __restrict__ br,
    const float* __restrict__ bw, const float* __restrict__ bf,
    const float* __restrict__ r_bias, const float* __restrict__ M_bias,
    float* __restrict__ out)
{
    extern __shared__ float sm[];
    float* M_s  = sm;                       // [G][128][20] 10240 (80B rows)
    float* z_s  = M_s + GQ * NQ * VQ;       // [32][G]  controller input (x|r|pad)
    float* h_s  = z_s + 32 * GQ;            // [100][G] controller hidden
    float* p_s  = h_s + CQ * GQ;            // [G][96]  head params
    float* h_t0 = p_s + GQ * PBLK;          // [G][128] [h|r|pad] buffer 0
    float* h_t1 = h_t0 + GQ * HTS;          // [G][128] [h|r|pad] buffer 1

    const int tid  = threadIdx.x;
    const int lane = tid & 31;
    const int g    = tid >> 5;              // warp == batch element
    const int b0   = blockIdx.x * GQ;

    // ---- hoisted per-thread constants ----
    float bcv = (tid < CQ) ? bc[tid] : 0.f;
    const float4* Wp4 = (const float4*)Ww4_g;
    int od = 66, st = 0, at = 0; float bsv = 0.f;
    {
        bool rh = (tid < 26);
        int c = rh ? tid : tid - 26;
        if (rh)            { Wp4 = (const float4*)Wr4_g + c; od = 26; bsv = br[c]; }
        else if (tid < 92) { Wp4 = (const float4*)Ww4_g + c; bsv = bw[c]; }
        if      (c < 20)  { st = (rh ? 0 : 32) + c;       at = 0; }
        else if (c == 20) { st = rh ? 24 : 26;            at = 1; }
        else if (c == 21) { st = rh ? 25 : 27;            at = 2; }
        else if (c < 25)  { st = (rh ? 20 : 28) + (c-22); at = 3; }
        else if (c == 25) { st = rh ? 23 : 31;            at = 4; }
        else if (c < 46)  { st = 52 + (c - 26);           at = 2; }
        else              { st = 72 + (c - 46);           at = 0; }
    }
    float bfv = bf[lane & 7];
    const float* pg = p_s + g * PBLK;

    // ---- init state: lane owns rows lane+32i of batch g ----
    float wprev_r[GQ];
    {
        const float4* Mb = (const float4*)M_bias;
        #pragma unroll
        for (int i = 0; i < GQ; i++) {
            int n = lane + 32 * i;
            wprev_r[i] = 0.f;
            float4* Mr = (float4*)&M_s[(g * NQ + n) * VQ];
            #pragma unroll
            for (int c2 = 0; c2 < 5; c2++) Mr[c2] = Mb[n * 5 + c2];
        }
    }
    if (tid < VQ * GQ) {                    // r0
        int gg = tid & 3, v = tid >> 2;
        z_s[(IQ + v) * GQ + gg] = r_bias[v];
    }
    if (tid < IQ * GQ) {                    // x_0
        int gg = tid / IQ, i = tid - gg * IQ;
        z_s[i * GQ + gg] = x[(b0 + gg) * TQ * IQ + i];
    }
    if (tid < 12) {                         // zero pads: z_s j=29..31
        int j = 29 + (tid >> 2), gg = tid & 3;
        z_s[j * GQ + gg] = 0.f;
    }
    if (tid < 64) {                         // zero pads: both h_t buffers [120..127]
        int gg = (tid >> 3) & 3;
        float* ht = (tid < 32) ? h_t0 : h_t1;
        ht[gg * HTS + 120 + (tid & 7)] = 0.f;
    }
    __syncthreads();

    for (int t = 0; t < TQ; t++) {
        float* h_cur  = (t & 1) ? h_t1 : h_t0;
        float* h_prev = (t & 1) ? h_t0 : h_t1;

        // ---- P1: controller h = tanh([x,r] @ Wc + bc)  (packed, dual accums) ----
        if (tid < CQ) {
            const float4*  wp = (const float4*)Wc4_g + tid;
            const double2* z2 = (const double2*)z_s;
            ull a01 = pk2(bcv), a23 = a01, b01 = 0ull, b23 = 0ull;
            #pragma unroll
            for (int jb = 0; jb < 8; jb += 2) {
                float4 w = wp[jb * CQ];
                double2 za = z2[4*jb+0], zb = z2[4*jb+1], zc = z2[4*jb+2], zd = z2[4*jb+3];
                ull wx = pk2(w.x), wy = pk2(w.y), wz = pk2(w.z), ww = pk2(w.w);
                a01 = ffma2(wx, d2l(za.x), a01); a23 = ffma2(wx, d2l(za.y), a23);
                a01 = ffma2(wy, d2l(zb.x), a01); a23 = ffma2(wy, d2l(zb.y), a23);
                a01 = ffma2(wz, d2l(zc.x), a01); a23 = ffma2(wz, d2l(zc.y), a23);
                a01 = ffma2(ww, d2l(zd.x), a01); a23 = ffma2(ww, d2l(zd.y), a23);
                float4 v = wp[(jb + 1) * CQ];
                double2 ze = z2[4*jb+4], zf = z2[4*jb+5], zg = z2[4*jb+6], zh = z2[4*jb+7];
                ull vx = pk2(v.x), vy = pk2(v.y), vz = pk2(v.z), vw = pk2(v.w);
                b01 = ffma2(vx, d2l(ze.x), b01); b23 = ffma2(vx, d2l(ze.y), b23);
                b01 = ffma2(vy, d2l(zf.x), b01); b23 = ffma2(vy, d2l(zf.y), b23);
                b01 = ffma2(vz, d2l(zg.x), b01); b23 = ffma2(vz, d2l(zg.y), b23);
                b01 = ffma2(vw, d2l(zh.x), b01); b23 = ffma2(vw, d2l(zh.y), b23);
            }
            a01 = fadd2(a01, b01); a23 = fadd2(a23, b23);
            float2 lo = upk2(a01), hi = upk2(a23);
            float h0 = ftanh_(lo.x), h1 = ftanh_(lo.y), h2 = ftanh_(hi.x), h3 = ftanh_(hi.y);
            *(float4*)&h_s[tid * GQ] = make_float4(h0, h1, h2, h3);
            h_cur[0 * HTS + tid] = h0; h_cur[1 * HTS + tid] = h1;
            h_cur[2 * HTS + tid] = h2; h_cur[3 * HTS + tid] = h3;
        }
        __syncthreads();

        // ---- Phase B: warps 0-2 do P2; warp 3 does out(t-1) + x prefetch ----
        if (tid < 92) {
            const double2* h2 = (const double2*)h_s;
            ull a01 = pk2(bsv), a23 = a01, b01 = 0ull, b23 = 0ull;
            #pragma unroll 4
            for (int jb = 0; jb < 24; jb += 2) {
                float4 w = Wp4[jb * od];
                double2 ha = h2[4*jb+0], hb = h2[4*jb+1], hc = h2[4*jb+2], hd = h2[4*jb+3];
                ull wx = pk2(w.x), wy = pk2(w.y), wz = pk2(w.z), ww = pk2(w.w);
                a01 = ffma2(wx, d2l(ha.x), a01); a23 = ffma2(wx, d2l(ha.y), a23);
                a01 = ffma2(wy, d2l(hb.x), a01); a23 = ffma2(wy, d2l(hb.y), a23);
                a01 = ffma2(wz, d2l(hc.x), a01); a23 = ffma2(wz, d2l(hc.y), a23);
                a01 = ffma2(ww, d2l(hd.x), a01); a23 = ffma2(ww, d2l(hd.y), a23);
                float4 v = Wp4[(jb + 1) * od];
                double2 he = h2[4*jb+4], hf = h2[4*jb+5], hg = h2[4*jb+6], hh = h2[4*jb+7];
                ull vx = pk2(v.x), vy = pk2(v.y), vz = pk2(v.z), vw = pk2(v.w);
                b01 = ffma2(vx, d2l(he.x), b01); b23 = ffma2(vx, d2l(he.y), b23);
                b01 = ffma2(vy, d2l(hf.x), b01); b23 = ffma2(vy, d2l(hf.y), b23);
                b01 = ffma2(vz, d2l(hg.x), b01); b23 = ffma2(vz, d2l(hg.y), b23);
                b01 = ffma2(vw, d2l(hh.x), b01); b23 = ffma2(vw, d2l(hh.y), b23);
            }
            {   // jb = 24 tail
                float4 w = Wp4[24 * od];
                double2 ha = h2[96], hb = h2[97], hc = h2[98], hd = h2[99];
                ull wx = pk2(w.x), wy = pk2(w.y), wz = pk2(w.z), ww = pk2(w.w);
                a01 = ffma2(wx, d2l(ha.x), a01); a23 = ffma2(wx, d2l(ha.y), a23);
                a01 = ffma2(wy, d2l(hb.x), a01); a23 = ffma2(wy, d2l(hb.y), a23);
                a01 = ffma2(wz, d2l(hc.x), a01); a23 = ffma2(wz, d2l(hc.y), a23);
                a01 = ffma2(ww, d2l(hd.x), a01); a23 = ffma2(ww, d2l(hd.y), a23);
            }
            a01 = fadd2(a01, b01); a23 = fadd2(a23, b23);
            float2 lo = upk2(a01), hi = upk2(a23);
            p_s[0 * PBLK + st] = apply_act(at, lo.x);
            p_s[1 * PBLK + st] = apply_act(at, lo.y);
            p_s[2 * PBLK + st] = apply_act(at, hi.x);
            p_s[3 * PBLK + st] = apply_act(at, hi.y);
        } else if (g == 3) {
            // out(t-1) for all 4 batch elements, from h_prev
            if (t > 0) {
                int o = lane & 7, part = lane >> 3;
                #pragma unroll
                for (int gg = 0; gg < GQ; gg++) {
                    const float4* wv  = (const float4*)Wf4_g + o;
                    const float4* hv4 = (const float4*)(h_prev + gg * HTS);
                    float acc = 0.f;
                    #pragma unroll
                    for (int jl = 0; jl < 8; jl++) {
                        int jb = part * 8 + jl;
                        float4 w = wv[jb * OQ];
                        float4 h = hv4[jb];
                        acc = fmaf(w.x, h.x, fmaf(w.y, h.y, fmaf(w.z, h.z, fmaf(w.w, h.w, acc))));
                    }
                    acc += __shfl_xor_sync(0xffffffffu, acc, 8);
                    acc += __shfl_xor_sync(0xffffffffu, acc, 16);
                    if (lane < 8)
                        out[((b0 + gg) * TQ + (t - 1)) * OQ + o] = fsigmoid_(acc + bfv);
                }
            }
            // prefetch x for t+1 (P1 of step t already consumed z_s x-part)
            if (t + 1 < TQ) {
                for (int idx = lane; idx < IQ * GQ; idx += 32) {
                    int gg = idx / IQ, i = idx - gg * IQ;
                    z_s[i * GQ + gg] = x[((b0 + gg) * TQ + (t + 1)) * IQ + i];
                }
            }
        }
        __syncthreads();

        // ======== warp-local phases (batch g); M in SMEM ========
        float4 srv = *(const float4*)(pg + 20);
        float4 bv  = *(const float4*)(pg + 24);
        float4 swv = *(const float4*)(pg + 28);
        float sr_i = __fdividef(1.f, srv.x + srv.y + srv.z);
        float s_r0 = srv.x * sr_i, s_r1 = srv.y * sr_i, s_r2 = srv.z * sr_i;
        float sw_i = __fdividef(1.f, swv.x + swv.y + swv.z);
        float s_w0 = swv.x * sw_i, s_w1 = swv.y * sw_i, s_w2 = swv.z * sw_i;

        // ---- C1: content addressing (packed dots, M loaded as double2) ----
        ull drp[4] = {0,0,0,0}, dwp[4] = {0,0,0,0}, n2p[4] = {0,0,0,0};
        ull kr2p = 0ull, kw2p = 0ull;
        const double2* krp = (const double2*)pg;
        const double2* kwp = (const double2*)(pg + 32);
        #pragma unroll
        for (int c = 0; c < 5; c++) {
            double2 krd = krp[c], kwd = kwp[c];
            ull kr01 = d2l(krd.x), kr23 = d2l(krd.y);
            ull kw01 = d2l(kwd.x), kw23 = d2l(kwd.y);
            kr2p = ffma2(kr01, kr01, kr2p); kr2p = ffma2(kr23, kr23, kr2p);
            kw2p = ffma2(kw01, kw01, kw2p); kw2p = ffma2(kw23, kw23, kw2p);
            #pragma unroll
            for (int i = 0; i < 4; i++) {
                double2 md = *(const double2*)&M_s[(g * NQ + lane + 32 * i) * VQ + c * 4];
                ull m01 = d2l(md.x), m23 = d2l(md.y);
                drp[i] = ffma2(kr01, m01, drp[i]); drp[i] = ffma2(kr23, m23, drp[i]);
                dwp[i] = ffma2(kw01, m01, dwp[i]); dwp[i] = ffma2(kw23, m23, dwp[i]);
                n2p[i] = ffma2(m01, m01, n2p[i]);  n2p[i] = ffma2(m23, m23, n2p[i]);
            }
        }
        float2 krt = upk2(kr2p), kwt = upk2(kw2p);
        float knr = sqrtf(krt.x + krt.y), knw = sqrtf(kwt.x + kwt.y);
        float er_r[4], ew_r[4], ser = 0.f, sew = 0.f;
        #pragma unroll
        for (int i = 0; i < 4; i++) {
            float2 dt = upk2(drp[i]), wt2 = upk2(dwp[i]), nt = upk2(n2p[i]);
            float mn = sqrtf(nt.x + nt.y);
            er_r[i] = __expf(bv.x * __fdividef(dt.x + dt.y, knr * mn + EPSQ));
            ew_r[i] = __expf(bv.z * __fdividef(wt2.x + wt2.y, knw * mn + EPSQ));
            ser += er_r[i]; sew += ew_r[i];
        }
        {   // packed (ser, sew) block reduction in ONE warp_sum2
            float2 ss = upk2(warp_sum2(pkf2(ser, sew)));
            ser = ss.x; sew = ss.y;
        }

        // ---- C2: read-head interp + conv via shfl + sharpen ----
        float ginv = bv.y * __fdividef(1.f, ser);
        float omg  = 1.f - bv.y;
        float wg_r[4];
        #pragma unroll
        for (int i = 0; i < 4; i++)
            wg_r[i] = fmaf(ginv, er_r[i], omg * wprev_r[i]);
        float wpr_r[4], ssp = 0.f;
        #pragma unroll
        for (int i = 0; i < 4; i++) {
            float tnp = (lane == 0)  ? wg_r[(i + 1) & 3] : wg_r[i];
            float tnm = (lane == 31) ? wg_r[(i + 3) & 3] : wg_r[i];
            float w_p = __shfl_sync(0xffffffffu, tnp, (lane + 1)  & 31);
            float w_m = __shfl_sync(0xffffffffu, tnm, (lane + 31) & 31);
            float ws  = s_r0 * w_p + s_r1 * wg_r[i] + s_r2 * w_m;
            wpr_r[i]  = __expf(srv.w * __logf(ws));
            ssp += wpr_r[i];
        }
        float sp = warp_sum(ssp);
        float invsp = __fdividef(1.f, sp + EPSQ);

        // ---- C3: write-head interp + conv via shfl + sharpen ----
        float gwinv = bv.w * __fdividef(1.f, sew);
        float omgsp = (1.f - bv.w) * invsp;
        float wt_r[4];
        #pragma unroll
        for (int i = 0; i < 4; i++)
            wt_r[i] = fmaf(gwinv, ew_r[i], omgsp * wpr_r[i]);
        float wpw_r[4], swp = 0.f;
        #pragma unroll
        for (int i = 0; i < 4; i++) {
            float tnp = (lane == 0)  ? wt_r[(i + 1) & 3] : wt_r[i];
            float tnm = (lane == 31) ? wt_r[(i + 3) & 3] : wt_r[i];
            float w_p = __shfl_sync(0xffffffffu, tnp, (lane + 1)  & 31);
            float w_m = __shfl_sync(0xffffffffu, tnm, (lane + 31) & 31);
            float ws  = s_w0 * w_p + s_w1 * wt_r[i] + s_w2 * w_m;
            wpw_r[i]  = __expf(swv.w * __logf(ws));
            swp += wpw_r[i];
        }
        float spw = warp_sum(swp);
        float invspw = __fdividef(1.f, spw + EPSQ);
        #pragma unroll
        for (int i = 0; i < 4; i++)
            wprev_r[i] = wpw_r[i] * invspw;

        // ---- C4: fused r-readout + M update (packed, M in SMEM) ----
        ull wr_d[4], ww_d[4], nww_d[4];
        #pragma unroll
        for (int i = 0; i < 4; i++) {
            wr_d[i]  = pk2(wpr_r[i] * invsp);
            ww_d[i]  = pk2(wprev_r[i]);
            nww_d[i] = pk2(-wprev_r[i]);
        }
        ull r01[5], r23[5];
        #pragma unroll
        for (int c = 0; c < 5; c++) {
            double2 ed = ((const double2*)(pg + 52))[c];
            double2 ad = ((const double2*)(pg + 72))[c];
            ull e01 = d2l(ed.x), e23 = d2l(ed.y);
            ull a01 = d2l(ad.x), a23 = d2l(ad.y);
            ull acc01 = 0ull, acc23 = 0ull;
            #pragma unroll
            for (int i = 0; i < 4; i++) {
                double2* mp = (double2*)&M_s[(g * NQ + lane + 32 * i) * VQ + c * 4];
                double2 md = *mp;
                ull m01 = d2l(md.x), m23 = d2l(md.y);
                acc01 = ffma2(wr_d[i], m01, acc01);
                acc23 = ffma2(wr_d[i], m23, acc23);
                ull nwe01 = fmul2(nww_d[i], e01), nwe23 = fmul2(nww_d[i], e23);
                m01 = ffma2(nwe01, m01, m01);   m23 = ffma2(nwe23, m23, m23);
                m01 = ffma2(ww_d[i], a01, m01); m23 = ffma2(ww_d[i], a23, m23);
                md.x = l2d(m01); md.y = l2d(m23);
                *mp = md;
            }
            r01[c] = warp_sum2(acc01);
            r23[c] = warp_sum2(acc23);
        }
        if (lane == 0) {
            #pragma unroll
            for (int c = 0; c < 5; c++) {
                float2 x01 = upk2(r01[c]), x23 = upk2(r23[c]);
                int v = c * 4;
                z_s[(IQ + v + 0) * GQ + g] = x01.x;
                z_s[(IQ + v + 1) * GQ + g] = x01.y;
                z_s[(IQ + v + 2) * GQ + g] = x23.x;
                z_s[(IQ + v + 3) * GQ + g] = x23.y;
                *(float4*)&h_cur[g * HTS + 100 + v] =
                    make_float4(x01.x, x01.y, x23.x, x23.y);
            }
        }
        __syncthreads();
    }

    // ---- final output: t = TQ-1, from buffer (TQ-1)&1 (each warp its g) ----
    {
        float* hp = ((TQ - 1) & 1) ? h_t1 : h_t0;
        int o = lane & 7, part = lane >> 3;
        const float4* wv  = (const float4*)Wf4_g + o;
        const float4* hv4 = (const float4*)(hp + g * HTS);
        float acc = 0.f;
        #pragma unroll
        for (int jl = 0; jl < 8; jl++) {
            int jb = part * 8 + jl;
            float4 w = wv[jb * OQ];
            float4 h = hv4[jb];
            acc = fmaf(w.x, h.x, fmaf(w.y, h.y, fmaf(w.z, h.z, fmaf(w.w, h.w, acc))));
        }
        acc += __shfl_xor_sync(0xffffffffu, acc, 8);
        acc += __shfl_xor_sync(0xffffffffu, acc, 16);
        if (lane < 8)
            out[((b0 + g) * TQ + (TQ - 1)) * OQ + o] = fsigmoid_(acc + bfv);
    }
}

extern "C" void kernel_launch(void* const* d_in, const int* in_sizes, int n_in,
                              void* d_out, int out_size) {
    const float* x      = (const float*)d_in[0];
    const float* Wc     = (const float*)d_in[1];
    const float* bc     = (const float*)d_in[2];
    const float* Wr     = (const float*)d_in[3];
    const float* br     = (const float*)d_in[4];
    const float* Ww     = (const float*)d_in[5];
    const float* bw     = (const float*)d_in[6];
    const float* Wf     = (const float*)d_in[7];
    const float* bf     = (const float*)d_in[8];
    const float* r_bias = (const float*)d_in[9];
    const float* M_bias = (const float*)d_in[10];

    int B = in_sizes[0] / (TQ * IQ);        // 2048
    int grid = B / GQ;                      // 512

    prep_kernel<<<65, 256>>>(Wc, Wr, Ww, Wf);   // 16496 elements

    size_t smem = (size_t)(GQ * NQ * VQ + 32 * GQ + CQ * GQ + GQ * PBLK
                           + 2 * GQ * HTS) * sizeof(float);   // 48704 B
    cudaFuncSetAttribute(ntm_kernel, cudaFuncAttributeMaxDynamicSharedMemorySize, (int)smem);

    ntm_kernel<<<grid, BLK, smem>>>(x, bc, br, bw, bf, r_bias, M_bias, (float*)d_out);
}